// round 9
// baseline (speedup 1.0000x reference)
#include <cuda_runtime.h>
#include <cstdint>

typedef unsigned long long u64;
#define NTOT 65536
#define BATCH 2

__device__ __align__(16) float g_qkv1[(size_t)BATCH*384*NTOT];
__device__ __align__(16) float g_sa  [(size_t)BATCH*NTOT];
__device__ __align__(16) float g_v2  [(size_t)BATCH*128*NTOT];
__device__ __align__(16) float g_z   [(size_t)BATCH*128*NTOT];
__device__ float g_S[4096];
__device__ float g_ssq_q[256];
__device__ float g_ssq_k[256];
__device__ float g_sumv[256];
__device__ float g_attn[4096];
__device__ float g_spec[256];
__device__ __align__(16) u64 g_wq2[128*384];
__device__ __align__(16) u64 g_wp2[128*128];

__device__ __forceinline__ void fma2(u64 &d, u64 a, u64 b){
    asm("fma.rn.f32x2 %0, %1, %2, %0;" : "+l"(d) : "l"(a), "l"(b));
}
__device__ __forceinline__ float2 unpack2(u64 v){
    float2 r; asm("mov.b64 {%0, %1}, %2;" : "=f"(r.x), "=f"(r.y) : "l"(v)); return r;
}
__device__ __forceinline__ void cp_async16(void* sdst, const void* gsrc){
    unsigned s = (unsigned)__cvta_generic_to_shared(sdst);
    asm volatile("cp.async.cg.shared.global [%0], [%1], 16;" :: "r"(s), "l"(gsrc));
}
__device__ __forceinline__ void cp_commit(){ asm volatile("cp.async.commit_group;"); }
__device__ __forceinline__ void cp_wait0(){ asm volatile("cp.async.wait_group 0;"); }
__device__ __forceinline__ float gelu_exact(float x){
    return 0.5f * x * (1.0f + erff(x * 0.70710678118654752f));
}

// Warp-wide 128-col row segment with halo: 32 lanes x 4 cols.
struct R6 { float lf; float4 a; float rt; };
__device__ __forceinline__ R6 row_load(int valid, const float* row, int col0, int ln){
    R6 r;
    if (!valid){ r.lf = r.rt = 0.f; r.a = make_float4(0.f,0.f,0.f,0.f); return r; }
    const float* rp = row + col0;
    r.a = __ldg((const float4*)(rp + 4*ln));
    r.lf = __shfl_up_sync(0xffffffffu, r.a.w, 1);
    r.rt = __shfl_down_sync(0xffffffffu, r.a.x, 1);
    if (ln == 0)  r.lf = (col0 > 0)        ? __ldg(rp - 1)   : 0.f;
    if (ln == 31) r.rt = (col0 + 128 < 256)? __ldg(rp + 128) : 0.f;
    return r;
}
__device__ __forceinline__ void row_app(float4& o, const R6& r, float w0, float w1, float w2){
    o.x += w0*r.lf  + w1*r.a.x + w2*r.a.y;
    o.y += w0*r.a.x + w1*r.a.y + w2*r.a.z;
    o.z += w0*r.a.y + w1*r.a.z + w2*r.a.w;
    o.w += w0*r.a.z + w1*r.a.w + w2*r.rt;
}

// 4-wide single-row stencil (R5 version, for k5a_z): t in [0,64), col0 = 0 here
__device__ __forceinline__ void conv_acc4(float4& o, int valid, const float* row, int t,
                                          float w0, float w1, float w2){
    if (!valid) return;
    float4 a = __ldg((const float4*)(row + 4*t));
    float lf = __shfl_up_sync(0xffffffffu, a.w, 1);
    float rt = __shfl_down_sync(0xffffffffu, a.x, 1);
    int lane = t & 31;
    if (lane == 0)  lf = (t == 32) ? __ldg(row + 127) : 0.f;
    if (lane == 31) rt = (t == 31) ? __ldg(row + 128) : 0.f;
    o.x += w0*lf  + w1*a.x + w2*a.y;
    o.y += w0*a.x + w1*a.y + w2*a.z;
    o.z += w0*a.y + w1*a.z + w2*a.w;
    o.w += w0*a.z + w1*a.w + w2*rt;
}
__device__ __forceinline__ float4 conv3x4(const float* base, int r, int t, const float* w){
    float4 o = make_float4(0.f, 0.f, 0.f, 0.f);
    conv_acc4(o, r > 0,   base + (size_t)(r-1)*256, t, w[0], w[1], w[2]);
    conv_acc4(o, 1,       base + (size_t)r*256,     t, w[3], w[4], w[5]);
    conv_acc4(o, r < 255, base + (size_t)(r+1)*256, t, w[6], w[7], w[8]);
    return o;
}

__global__ void k_prep(const float* __restrict__ qkv_w, const float* __restrict__ proj_w){
    int idx = blockIdx.x * 256 + threadIdx.x;
    if (idx < 49152){
        int o = idx % 384, i = idx / 384;
        unsigned b = __float_as_uint(qkv_w[o*128 + i]);
        g_wq2[idx] = ((u64)b << 32) | (u64)b;
    } else if (idx < 65536){
        int k = idx - 49152;
        int i = k >> 7, o = k & 127;
        unsigned b = __float_as_uint(proj_w[o*128 + i]);
        g_wp2[k] = ((u64)b << 32) | (u64)b;
    } else {
        int j = idx - 65536;
        if (j < 4096) g_S[j] = 0.f;
        else if (j < 4352) g_ssq_q[j-4096] = 0.f;
        else if (j < 4608) g_ssq_k[j-4352] = 0.f;
        else if (j < 4864) g_sumv [j-4608] = 0.f;
    }
}

__global__ void __launch_bounds__(256) k_sa(const float* __restrict__ y,
                                            const float* __restrict__ w1,
                                            const float* __restrict__ w2,
                                            const float* __restrict__ w3){
    __shared__ float sW1[128][16];
    __shared__ float sW2[16][16];
    __shared__ float sW3[16];
    int tid = threadIdx.x;
    int b = blockIdx.y;
    for (int i = tid; i < 2048; i += 256){ int c = i >> 4, j = i & 15; sW1[c][j] = w1[j*128 + c]; }
    (&sW2[0][0])[tid] = w2[tid];
    if (tid < 16) sW3[tid] = w3[tid];
    __syncthreads();

    int n0 = (blockIdx.x * 256 + tid) * 4;
    float acc[4][16];
#pragma unroll
    for (int p = 0; p < 4; p++)
#pragma unroll
        for (int j = 0; j < 16; j++) acc[p][j] = 0.f;

    const float* yb = y + (size_t)b * 128 * NTOT + n0;
    for (int c = 0; c < 128; c++){
        float4 yv = *(const float4*)(yb + (size_t)c * NTOT);
#pragma unroll
        for (int j = 0; j < 16; j++){
            float w = sW1[c][j];
            acc[0][j] += w * yv.x; acc[1][j] += w * yv.y;
            acc[2][j] += w * yv.z; acc[3][j] += w * yv.w;
        }
    }
    float out[4];
#pragma unroll
    for (int p = 0; p < 4; p++){
        float t2[16];
#pragma unroll
        for (int i = 0; i < 16; i++){
            float s = 0.f;
#pragma unroll
            for (int j = 0; j < 16; j++) s += sW2[i][j] * fmaxf(acc[p][j], 0.f);
            t2[i] = fmaxf(s, 0.f);
        }
        float s3 = 0.f;
#pragma unroll
        for (int j = 0; j < 16; j++) s3 += sW3[j] * t2[j];
        out[p] = 1.f / (1.f + expf(-s3));
    }
    *(float4*)(g_sa + (size_t)b * NTOT + n0) = make_float4(out[0], out[1], out[2], out[3]);
}

// C[M,N] = W[M,128] @ X[128,N] per batch; FFMA2 8x8 tile, cp.async double buffer
__global__ void __launch_bounds__(256, 2) k_gemm(const u64* __restrict__ w2,
                                                 const float* __restrict__ X,
                                                 float* __restrict__ C, int M){
    __shared__ u64 ws[2][16][128];
    __shared__ u64 xs[2][16][64];

    int tid = threadIdx.x;
    int b = blockIdx.z;
    int obase = blockIdx.y * 128;
    int nbase = blockIdx.x * 128;
    const float* x = X + (size_t)b * 128 * NTOT;
    float* c = C + (size_t)b * M * NTOT;
    int to8 = (tid >> 4) * 8;
    int tn4 = (tid & 15) * 4;

    auto load_chunk = [&](int kc, int buf){
#pragma unroll
        for (int t = 0; t < 4; t++){
            int e = t * 256 + tid;
            int k = e >> 6;
            int o = (2 * e) & 127;
            cp_async16(&ws[buf][k][o], w2 + (size_t)(kc*16 + k) * M + obase + o);
        }
#pragma unroll
        for (int t = 0; t < 2; t++){
            int e = t * 256 + tid;
            int k = e >> 5;
            int p = (2 * e) & 63;
            cp_async16(&xs[buf][k][p], x + (size_t)(kc*16 + k) * NTOT + nbase + 2*p);
        }
        cp_commit();
    };

    u64 acc[8][4];
#pragma unroll
    for (int o = 0; o < 8; o++)
#pragma unroll
        for (int p = 0; p < 4; p++) acc[o][p] = 0ULL;

    load_chunk(0, 0);
    cp_wait0(); __syncthreads();

    for (int kc = 0; kc < 8; kc++){
        int buf = kc & 1;
        if (kc < 7) load_chunk(kc + 1, buf ^ 1);
#pragma unroll
        for (int k = 0; k < 16; k++){
            u64 wv[8], xv[4];
#pragma unroll
            for (int j = 0; j < 4; j++){
                ulonglong2 t = *(const ulonglong2*)&ws[buf][k][to8 + 2*j];
                wv[2*j] = t.x; wv[2*j+1] = t.y;
            }
            {
                ulonglong2 t0 = *(const ulonglong2*)&xs[buf][k][tn4];
                ulonglong2 t1 = *(const ulonglong2*)&xs[buf][k][tn4 + 2];
                xv[0] = t0.x; xv[1] = t0.y; xv[2] = t1.x; xv[3] = t1.y;
            }
#pragma unroll
            for (int o = 0; o < 8; o++)
#pragma unroll
                for (int p = 0; p < 4; p++)
                    fma2(acc[o][p], wv[o], xv[p]);
        }
        if (kc < 7){ cp_wait0(); __syncthreads(); }
    }

#pragma unroll
    for (int o = 0; o < 8; o++){
        float2 f0 = unpack2(acc[o][0]), f1 = unpack2(acc[o][1]);
        float2 f2 = unpack2(acc[o][2]), f3 = unpack2(acc[o][3]);
        float* dst = c + (size_t)(obase + to8 + o) * NTOT + nbase + (tid & 15) * 8;
        *(float4*)(dst)     = make_float4(f0.x, f0.y, f1.x, f1.y);
        *(float4*)(dst + 4) = make_float4(f2.x, f2.y, f3.x, f3.y);
    }
}

// fused dwconv3x3 + sa gate + reductions + v write; 2 output rows x 128 cols per block.
__global__ void __launch_bounds__(256) k2_dw(const float* __restrict__ qkv_dw_w){
    int tid = threadIdx.x;
    int wp = tid >> 5, ln = tid & 31;
    int rp = blockIdx.x >> 1, nh = blockIdx.x & 1;
    int h = blockIdx.y, b = blockIdx.z;
    int r0 = 2*rp;
    int col0 = nh * 128;

    __shared__ __align__(16) float qs[16][2][132];
    __shared__ __align__(16) float ks[16][2][132];
    __shared__ float sdw[48][9];
    __shared__ __align__(16) float s_sa[2][128];
    __shared__ float s_ssq_q[16], s_ssq_k[16], s_vsum[16];

    if (tid < 64){
        int rr = tid >> 5, pp = tid & 31;
        *(float4*)&s_sa[rr][4*pp] =
            *(const float4*)(g_sa + (size_t)b*NTOT + (size_t)(r0+rr)*256 + col0 + 4*pp);
    }
    for (int idx = tid; idx < 432; idx += 256){
        int lc = idx / 9, j = idx % 9;
        int ch = (lc < 16) ? (h*16 + lc) : (lc < 32 ? (128 + h*16 + (lc-16)) : (256 + h*16 + (lc-32)));
        sdw[lc][j] = qkv_dw_w[ch*9 + j];
    }
    if (tid < 16){ s_ssq_q[tid] = 0.f; s_ssq_k[tid] = 0.f; s_vsum[tid] = 0.f; }
    __syncthreads();

    float4 sa0 = *(const float4*)&s_sa[0][4*ln];
    float4 sa1 = *(const float4*)&s_sa[1][4*ln];

#pragma unroll 1
    for (int it = 0; it < 6; it++){
        int lc = wp + 8*it;
        int ch = (lc < 16) ? (h*16 + lc) : (lc < 32 ? (128 + h*16 + (lc-16)) : (256 + h*16 + (lc-32)));
        const float* base = g_qkv1 + ((size_t)b*384 + ch) * NTOT;
        R6 rm = row_load(r0 > 0,     base + (size_t)(r0-1)*256, col0, ln);
        R6 ra = row_load(1,          base + (size_t)(r0  )*256, col0, ln);
        R6 rb = row_load(1,          base + (size_t)(r0+1)*256, col0, ln);
        R6 rc = row_load(r0+2 < 256, base + (size_t)(r0+2)*256, col0, ln);
        const float* w = sdw[lc];
        float4 z0 = make_float4(0.f,0.f,0.f,0.f), z1 = z0;
        row_app(z0, rm, w[0],w[1],w[2]); row_app(z0, ra, w[3],w[4],w[5]); row_app(z0, rb, w[6],w[7],w[8]);
        row_app(z1, ra, w[0],w[1],w[2]); row_app(z1, rb, w[3],w[4],w[5]); row_app(z1, rc, w[6],w[7],w[8]);

        if (lc < 16){
            z0.x *= sa0.x; z0.y *= sa0.y; z0.z *= sa0.z; z0.w *= sa0.w;
            z1.x *= sa1.x; z1.y *= sa1.y; z1.z *= sa1.z; z1.w *= sa1.w;
            *(float4*)&qs[lc][0][4*ln] = z0;
            *(float4*)&qs[lc][1][4*ln] = z1;
            float sq = z0.x*z0.x + z0.y*z0.y + z0.z*z0.z + z0.w*z0.w
                     + z1.x*z1.x + z1.y*z1.y + z1.z*z1.z + z1.w*z1.w;
#pragma unroll
            for (int o = 16; o; o >>= 1) sq += __shfl_down_sync(0xffffffffu, sq, o);
            if (ln == 0) atomicAdd(&s_ssq_q[lc], sq);
        } else if (lc < 32){
            *(float4*)&ks[lc-16][0][4*ln] = z0;
            *(float4*)&ks[lc-16][1][4*ln] = z1;
            float sq = z0.x*z0.x + z0.y*z0.y + z0.z*z0.z + z0.w*z0.w
                     + z1.x*z1.x + z1.y*z1.y + z1.z*z1.z + z1.w*z1.w;
#pragma unroll
            for (int o = 16; o; o >>= 1) sq += __shfl_down_sync(0xffffffffu, sq, o);
            if (ln == 0) atomicAdd(&s_ssq_k[lc-16], sq);
        } else {
            float* dst = g_v2 + ((size_t)b*128 + h*16 + (lc-32)) * NTOT + (size_t)r0*256 + col0;
            *(float4*)(dst + 4*ln)       = z0;
            *(float4*)(dst + 256 + 4*ln) = z1;
            float sv = z0.x + z0.y + z0.z + z0.w + z1.x + z1.y + z1.z + z1.w;
#pragma unroll
            for (int o = 16; o; o >>= 1) sv += __shfl_down_sync(0xffffffffu, sv, o);
            if (ln == 0) atomicAdd(&s_vsum[lc-32], sv);
        }
    }
    __syncthreads();

    int c = tid >> 4, d = tid & 15;
    float s = 0.f;
#pragma unroll 2
    for (int rr = 0; rr < 2; rr++)
#pragma unroll 8
        for (int i = 0; i < 32; i++){
            float4 qv = *(const float4*)&qs[c][rr][4*i];
            float4 kv = *(const float4*)&ks[d][rr][4*i];
            s += qv.x*kv.x + qv.y*kv.y + qv.z*kv.z + qv.w*kv.w;
        }
    atomicAdd(&g_S[((b*8 + h)*16 + c)*16 + d], s);

    if (tid < 16){
        atomicAdd(&g_ssq_q[b*128 + h*16 + tid], s_ssq_q[tid]);
        atomicAdd(&g_ssq_k[b*128 + h*16 + tid], s_ssq_k[tid]);
        atomicAdd(&g_sumv [b*128 + h*16 + tid], s_vsum[tid]);
    }
}

// softmax + spectral MLP (one block, 256 threads)
__global__ void k4_small(const float* __restrict__ sp_w1, const float* __restrict__ sp_w2,
                         const float* __restrict__ sp_w3, const float* __restrict__ temp){
    __shared__ float pooled[2][128];
    __shared__ float t1s[2][16], t2s[2][16];
    int t = threadIdx.x;
    int b = t >> 7, row = t & 127, h = row >> 4, c = row & 15;

    float nq = fmaxf(sqrtf(g_ssq_q[b*128 + row]), 1e-12f);
    float tmp = temp[h];
    float logits[16];
    float mx = -1e30f;
#pragma unroll
    for (int d = 0; d < 16; d++){
        float nk = fmaxf(sqrtf(g_ssq_k[b*128 + h*16 + d]), 1e-12f);
        float L = g_S[((b*8 + h)*16 + c)*16 + d] / (nq * nk) * tmp;
        logits[d] = L; mx = fmaxf(mx, L);
    }
    float se = 0.f;
#pragma unroll
    for (int d = 0; d < 16; d++){ float e = expf(logits[d] - mx); logits[d] = e; se += e; }
    float inv = 1.f / se;
    float pool = 0.f;
#pragma unroll
    for (int d = 0; d < 16; d++){
        float a = logits[d] * inv;
        g_attn[b*2048 + (h*16 + c)*16 + d] = a;
        pool += a * g_sumv[b*128 + h*16 + d];
    }
    pooled[b][row] = pool * (1.f / 65536.f);
    __syncthreads();
    if (t < 32){
        int bb = t >> 4, j = t & 15;
        float s = 0.f;
        for (int c2 = 0; c2 < 128; c2++) s += sp_w1[j*128 + c2] * pooled[bb][c2];
        t1s[bb][j] = gelu_exact(s);
    }
    __syncthreads();
    if (t < 32){
        int bb = t >> 4, j = t & 15;
        float s = 0.f;
#pragma unroll
        for (int i = 0; i < 16; i++) s += sp_w2[j*16 + i] * t1s[bb][i];
        t2s[bb][j] = gelu_exact(s);
    }
    __syncthreads();
    {
        int bb = t >> 7, ch = t & 127;
        float s = 0.f;
#pragma unroll
        for (int j = 0; j < 16; j++) s += sp_w3[ch*16 + j] * t2s[bb][j];
        g_spec[bb*128 + ch] = 1.f / (1.f + expf(-s));
    }
}

// z = blockdiag(attn) @ v + spec * dwconv3x3(y); 4-wide, v tile staged in smem per head
__global__ void __launch_bounds__(256) k5a_z(const float* __restrict__ y,
                                             const float* __restrict__ dw_w){
    int tid = threadIdx.x;
    int r = blockIdx.x, b = blockIdx.y;
    int g = tid >> 6, t = tid & 63;
    __shared__ float s_attn[2048];
    __shared__ float s_spec[128];
    __shared__ float s_dw[128][9];
    __shared__ __align__(16) float sv[16][256];
    for (int i = tid; i < 2048; i += 256) s_attn[i] = g_attn[b*2048 + i];
    for (int i = tid; i < 1152; i += 256) (&s_dw[0][0])[i] = dw_w[i];
    if (tid < 128) s_spec[tid] = g_spec[b*128 + tid];
    __syncthreads();

    for (int h = 0; h < 8; h++){
        for (int i = tid; i < 1024; i += 256){
            int d = i >> 6, p = i & 63;
            *(float4*)&sv[d][4*p] =
                *(const float4*)(g_v2 + ((size_t)b*128 + h*16 + d) * NTOT + r*256 + 4*p);
        }
        __syncthreads();
#pragma unroll
        for (int cc = 0; cc < 4; cc++){
            int c = cc*4 + g;
            int ch = h*16 + c;
            const float* ybase = y + ((size_t)b*128 + ch) * NTOT;
            float4 z = conv3x4(ybase, r, t, s_dw[ch]);
            float sp = s_spec[ch];
            z.x *= sp; z.y *= sp; z.z *= sp; z.w *= sp;
            const float* arow = &s_attn[ch * 16];
#pragma unroll
            for (int d = 0; d < 16; d++){
                float a = arow[d];
                float4 vd = *(const float4*)&sv[d][4*t];
                z.x += a*vd.x; z.y += a*vd.y; z.z += a*vd.z; z.w += a*vd.w;
            }
            *(float4*)(g_z + ((size_t)b*128 + ch) * NTOT + r*256 + 4*t) = z;
        }
        __syncthreads();
    }
}

extern "C" void kernel_launch(void* const* d_in, const int* in_sizes, int n_in,
                              void* d_out, int out_size){
    const float* x        = (const float*)d_in[0];
    const float* y        = (const float*)d_in[1];
    const float* qkv_w    = (const float*)d_in[2];
    const float* qkv_dw_w = (const float*)d_in[3];
    const float* proj_w   = (const float*)d_in[4];
    const float* sa_w1    = (const float*)d_in[5];
    const float* sa_w2    = (const float*)d_in[6];
    const float* sa_w3    = (const float*)d_in[7];
    const float* sp_w1    = (const float*)d_in[8];
    const float* sp_w2    = (const float*)d_in[9];
    const float* sp_w3    = (const float*)d_in[10];
    const float* dw_w     = (const float*)d_in[11];
    const float* temp     = (const float*)d_in[12];
    float* out = (float*)d_out;

    u64 *wq2, *wp2;
    float *qkv1, *z;
    cudaGetSymbolAddress((void**)&wq2,  g_wq2);
    cudaGetSymbolAddress((void**)&wp2,  g_wp2);
    cudaGetSymbolAddress((void**)&qkv1, g_qkv1);
    cudaGetSymbolAddress((void**)&z,    g_z);

    k_prep<<<276, 256>>>(qkv_w, proj_w);
    k_sa<<<dim3(64, 2), 256>>>(y, sa_w1, sa_w2, sa_w3);
    k_gemm<<<dim3(512, 3, 2), 256>>>(wq2, x, qkv1, 384);
    k2_dw<<<dim3(256, 8, 2), 256>>>(qkv_dw_w);
    k4_small<<<1, 256>>>(sp_w1, sp_w2, sp_w3, temp);
    k5a_z<<<dim3(256, 2), 256>>>(y, dw_w);
    k_gemm<<<dim3(512, 1, 2), 256>>>(wp2, z, out, 128);
}